// round 15
// baseline (speedup 1.0000x reference)
#include <cuda_runtime.h>
#include <cuda_fp16.h>

#define NN  100000
#define NE  3200000
#define CIN 128
#define HID 16
#define MAXDEG 128   // binomial(3.2M,1e-5): mean 32, max ~57 over 100K nodes

// Scratch (no allocations allowed).
__device__ int   g_degi[NN];             // in-degree (excl. self)
__device__ float g_dinv[NN];             // rsqrt(1+deg)
__device__ int   g_nbr2[NN * MAXDEG];    // fixed-stride CSR: sources per target
__device__ half2 g_feat[NN * 8];         // layer-1 pre-scaled features (fp16 rows, 32B)
__device__ half2 g_feat2[NN * 8];        // layer-2 pre-scaled features (fp16 rows, 32B)
__device__ float g_agg[NN * HID];        // self-loop term (fp32)
__device__ uint4 g_h2[NN * 2];           // final embeddings (fp16 rows, 32B)
__device__ int   g_is64;                 // 1 if edge_index is int64, 0 if int32

__device__ __forceinline__ int clampi(long long v) {
    v = v < 0 ? 0 : (v >= NN ? NN - 1 : v);
    return (int)v;
}

__device__ __forceinline__ int4 load_idx4(const void* ei, long long pos, int is64) {
    if (!is64) {
        int4 t = __ldg((const int4*)((const int*)ei + pos));
        return make_int4(clampi(t.x), clampi(t.y), clampi(t.z), clampi(t.w));
    } else {
        longlong2 a = __ldg((const longlong2*)((const long long*)ei + pos));
        longlong2 b = __ldg((const longlong2*)((const long long*)ei + pos + 2));
        return make_int4(clampi(a.x), clampi(a.y), clampi(b.x), clampi(b.y));
    }
}

__device__ __forceinline__ int load_idx1(const void* ei, long long pos, int is64) {
    long long v = is64 ? __ldg((const long long*)ei + pos)
                       : (long long)__ldg((const int*)ei + pos);
    return clampi(v);
}

// #1: zero counters + (block 0) dtype detection.
__global__ void k_init(const void* ei) {
    if (blockIdx.x == 0) {
        __shared__ int bad;
        if (threadIdx.x == 0) bad = 0;
        __syncthreads();
        long long pos = (long long)threadIdx.x * (NE / 256);
        long long v = ((const long long*)ei)[pos];
        if (v < 0 || v >= NN) atomicOr(&bad, 1);
        __syncthreads();
        if (threadIdx.x == 0) g_is64 = bad ? 0 : 1;
    }
    int i = blockIdx.x * blockDim.x + threadIdx.x;
    if (i < NN) g_degi[i] = 0;
}

// #2: count degrees AND scatter source ids into fixed-stride segments.
__global__ void k_deg_store(const void* __restrict__ ei) {
    int t = blockIdx.x * blockDim.x + threadIdx.x;
    long long e = (long long)t * 4;
    if (e >= NE) return;
    int is64 = g_is64;
    int4 r4 = load_idx4(ei, e, is64);
    int4 c4 = load_idx4(ei, (long long)NE + e, is64);
    int rr[4] = {r4.x, r4.y, r4.z, r4.w};
    int cc[4] = {c4.x, c4.y, c4.z, c4.w};
    #pragma unroll
    for (int k = 0; k < 4; k++) {
        int rk = atomicAdd(&g_degi[cc[k]], 1);
        if (rk < MAXDEG) g_nbr2[cc[k] * MAXDEG + rk] = rr[k];
    }
}

// #3: layer-1 transform (16 nodes/block) + dinv computation.
#define XS_STR 132
__global__ void k_xform1(const float* __restrict__ x, const float* __restrict__ W1) {
    __shared__ float sX[16 * XS_STR];
    __shared__ float sWt[HID * XS_STR];
    const float* xb = x + (size_t)blockIdx.x * 16 * CIN;
    #pragma unroll
    for (int L = threadIdx.x; L < 16 * CIN; L += 256) {
        int n = L >> 7, k = L & 127;
        sX[n * XS_STR + k] = xb[L];
    }
    #pragma unroll
    for (int L = threadIdx.x; L < CIN * HID; L += 256) {
        int k = L >> 4, j = L & 15;
        sWt[j * XS_STR + k] = W1[L];
    }
    __syncthreads();
    int nloc = threadIdx.x >> 4;
    int j    = threadIdx.x & 15;
    int node = blockIdx.x * 16 + nloc;
    const float4* xr = (const float4*)(sX  + nloc * XS_STR);
    const float4* wr = (const float4*)(sWt + j    * XS_STR);
    float acc = 0.f;
    #pragma unroll
    for (int k4 = 0; k4 < CIN / 4; k4++) {
        float4 xv = xr[k4];
        float4 wv = wr[k4];
        acc = fmaf(xv.x, wv.x, acc);
        acc = fmaf(xv.y, wv.y, acc);
        acc = fmaf(xv.z, wv.z, acc);
        acc = fmaf(xv.w, wv.w, acc);
    }
    float dv = rsqrtf(1.0f + (float)g_degi[node]);
    if (j == 0) g_dinv[node] = dv;
    float v = acc * dv;
    int tid = blockIdx.x * 256 + threadIdx.x;
    ((__half*)g_feat)[tid] = __float2half(v);
    g_agg[tid] = v;
}

// #4: pull layer 1 + fused layer-2. OCTET layout: 8 lanes per node, 4 nodes/warp.
// Each lane owns one half2 column of its node; no cross-lane reduction needed.
__global__ void k_pull1(const float* __restrict__ W2, const float* __restrict__ b1) {
    __shared__ float2 sW2[HID * 8];   // sW2[k*8+jj] = (W2[k][2jj], W2[k][2jj+1])
    __shared__ float2 sb2[8];
    for (int L = threadIdx.x; L < HID * 8; L += blockDim.x) {
        int k = L >> 3, jj = L & 7;
        sW2[L] = make_float2(W2[k * HID + 2*jj], W2[k * HID + 2*jj + 1]);
    }
    if (threadIdx.x < 8)
        sb2[threadIdx.x] = make_float2(b1[2*threadIdx.x], b1[2*threadIdx.x + 1]);
    __syncthreads();

    int gtid = blockIdx.x * blockDim.x + threadIdx.x;
    int node = gtid >> 3;                 // 8 lanes per node
    if (node >= NN) return;
    int lane = threadIdx.x & 31;
    int jj   = lane & 7;
    int ob   = lane & 24;                 // octet base lane (0,8,16,24)
    int start = node * MAXDEG;
    int deg   = min(g_degi[node], MAXDEG);
    float2 acc = make_float2(0.f, 0.f);
    for (int base = 0; base < deg; base += 8) {
        int myn = (base + jj < deg) ? g_nbr2[start + base + jj] : 0;
        int lim = min(8, deg - base);
        #pragma unroll
        for (int k = 0; k < 8; k++) {
            if (k >= lim) break;
            int r = __shfl_sync(0xffffffffu, myn, ob + k);
            float2 f = __half22float2(g_feat[(size_t)r * 8 + jj]);
            acc.x += f.x; acc.y += f.y;
        }
    }
    // ---- fused layer-2 transform (each lane: columns 2jj, 2jj+1 of its node) ----
    float dv = g_dinv[node];
    float2 ag = *(const float2*)(g_agg + (size_t)node * HID + 2*jj);
    float2 bb = sb2[jj];
    float2 hv;
    hv.x = fmaxf(fmaf(dv, ag.x + acc.x, bb.x), 0.f);
    hv.y = fmaxf(fmaf(dv, ag.y + acc.y, bb.y), 0.f);
    float2 ov = make_float2(0.f, 0.f);
    #pragma unroll
    for (int kk = 0; kk < 8; kk++) {
        float hx = __shfl_sync(0xffffffffu, hv.x, ob + kk);   // h[2kk]
        float hy = __shfl_sync(0xffffffffu, hv.y, ob + kk);   // h[2kk+1]
        float2 w0 = sW2[(2*kk    ) * 8 + jj];
        float2 w1 = sW2[(2*kk + 1) * 8 + jj];
        ov.x = fmaf(hx, w0.x, fmaf(hy, w1.x, ov.x));
        ov.y = fmaf(hx, w0.y, fmaf(hy, w1.y, ov.y));
    }
    ov.x *= dv; ov.y *= dv;
    g_feat2[(size_t)node * 8 + jj] = __floats2half2_rn(ov.x, ov.y);
    *(float2*)(g_agg + (size_t)node * HID + 2*jj) = ov;
}

// #5: pull layer 2 + fused h2 (fp16 out). Same octet layout.
__global__ void k_pull2(const float* __restrict__ b2) {
    __shared__ float2 sb2[8];
    if (threadIdx.x < 8)
        sb2[threadIdx.x] = make_float2(b2[2*threadIdx.x], b2[2*threadIdx.x + 1]);
    __syncthreads();
    int gtid = blockIdx.x * blockDim.x + threadIdx.x;
    int node = gtid >> 3;
    if (node >= NN) return;
    int lane = threadIdx.x & 31;
    int jj   = lane & 7;
    int ob   = lane & 24;
    int start = node * MAXDEG;
    int deg   = min(g_degi[node], MAXDEG);
    float2 acc = make_float2(0.f, 0.f);
    for (int base = 0; base < deg; base += 8) {
        int myn = (base + jj < deg) ? g_nbr2[start + base + jj] : 0;
        int lim = min(8, deg - base);
        #pragma unroll
        for (int k = 0; k < 8; k++) {
            if (k >= lim) break;
            int r = __shfl_sync(0xffffffffu, myn, ob + k);
            float2 f = __half22float2(g_feat2[(size_t)r * 8 + jj]);
            acc.x += f.x; acc.y += f.y;
        }
    }
    float dv = g_dinv[node];
    float2 ag = *(const float2*)(g_agg + (size_t)node * HID + 2*jj);
    float2 bb = sb2[jj];
    float hx = fmaf(dv, ag.x + acc.x, bb.x);
    float hy = fmaf(dv, ag.y + acc.y, bb.y);
    ((half2*)g_h2)[(size_t)node * 8 + jj] = __floats2half2_rn(hx, hy);
}

// #6: score, 2 lanes per edge; fp16 rows = 1 sector per row.
__global__ void k_score(const void* __restrict__ ei, float* __restrict__ out) {
    int t = blockIdx.x * blockDim.x + threadIdx.x;
    long long e = t >> 1;
    if (e >= NE) return;
    int p = t & 1;
    int is64 = g_is64;
    int r = load_idx1(ei, e, is64);
    int c = load_idx1(ei, (long long)NE + e, is64);
    uint4 av = __ldg(&g_h2[(size_t)r * 2 + p]);
    uint4 bv = __ldg(&g_h2[(size_t)c * 2 + p]);
    const half2* ah = (const half2*)&av;
    const half2* bh = (const half2*)&bv;
    float s = 0.f;
    #pragma unroll
    for (int q = 0; q < 4; q++) {
        float2 a = __half22float2(ah[q]);
        float2 b = __half22float2(bh[q]);
        s = fmaf(a.x, b.x, fmaf(a.y, b.y, s));
    }
    s += __shfl_xor_sync(0xffffffffu, s, 1);
    if (p == 0) out[e] = 1.0f / (1.0f + __expf(-s));
}

extern "C" void kernel_launch(void* const* d_in, const int* in_sizes, int n_in,
                              void* d_out, int out_size) {
    const float* x  = nullptr;
    const void*  ei = nullptr;
    const float* W1 = nullptr;
    const float* b1 = nullptr;
    const float* W2 = nullptr;
    const float* b2 = nullptr;
    for (int i = 0; i < n_in; i++) {
        long long n = in_sizes[i];
        if      (n == (long long)NN * CIN)      x  = (const float*)d_in[i];
        else if (n == 2LL * NE)                 ei = d_in[i];
        else if (n == CIN * HID)                W1 = (const float*)d_in[i];
        else if (n == HID * HID)                W2 = (const float*)d_in[i];
        else if (n == HID) { if (!b1) b1 = (const float*)d_in[i]; else b2 = (const float*)d_in[i]; }
    }
    float* out = (float*)d_out;

    const int TB  = 256;
    const int gn  = (NN + TB - 1) / TB;
    const int ge4 = (NE / 4 + TB - 1) / TB;
    const int go  = (NN * 8 + TB - 1) / TB;             // 8 lanes per node
    const int gs  = ((long long)NE * 2 + TB - 1) / TB;  // 2 lanes per edge

    k_init     <<<gn,  TB>>>(ei);           // #1 (zero + detect)
    k_deg_store<<<ge4, TB>>>(ei);           // #2
    k_xform1   <<<NN/16, TB>>>(x, W1);      // #3 (+ dinv)
    k_pull1    <<<go,  TB>>>(W2, b1);       // #4  <- profiler slot
    k_pull2    <<<go,  TB>>>(b2);           // #5
    k_score    <<<gs,  TB>>>(ei, out);      // #6
}

// round 16
// speedup vs baseline: 1.2135x; 1.2135x over previous
#include <cuda_runtime.h>
#include <cuda_fp16.h>

#define NN  100000
#define NE  3200000
#define CIN 128
#define HID 16
#define MAXDEG 128   // binomial(3.2M,1e-5): mean 32, max ~57 over 100K nodes

// Scratch (no allocations allowed).
__device__ int   g_degi[NN];             // in-degree (excl. self)
__device__ float g_dinv[NN];             // rsqrt(1+deg)
__device__ int   g_nbr2[NN * MAXDEG];    // fixed-stride CSR: sources per target
__device__ half2 g_feat[NN * 8];         // layer-1 pre-scaled features (fp16 rows, 32B)
__device__ half2 g_feat2[NN * 8];        // layer-2 pre-scaled features (fp16 rows, 32B)
__device__ float g_agg[NN * HID];        // self-loop term (fp32)
__device__ uint4 g_h2[NN * 2];           // final embeddings (fp16 rows, 32B)
__device__ int   g_is64;                 // 1 if edge_index is int64, 0 if int32

__device__ __forceinline__ int clampi(long long v) {
    v = v < 0 ? 0 : (v >= NN ? NN - 1 : v);
    return (int)v;
}

__device__ __forceinline__ int4 load_idx4(const void* ei, long long pos, int is64) {
    if (!is64) {
        int4 t = __ldg((const int4*)((const int*)ei + pos));
        return make_int4(clampi(t.x), clampi(t.y), clampi(t.z), clampi(t.w));
    } else {
        longlong2 a = __ldg((const longlong2*)((const long long*)ei + pos));
        longlong2 b = __ldg((const longlong2*)((const long long*)ei + pos + 2));
        return make_int4(clampi(a.x), clampi(a.y), clampi(b.x), clampi(b.y));
    }
}

__device__ __forceinline__ int load_idx1(const void* ei, long long pos, int is64) {
    long long v = is64 ? __ldg((const long long*)ei + pos)
                       : (long long)__ldg((const int*)ei + pos);
    return clampi(v);
}

// #1: zero counters + (block 0) dtype detection.
__global__ void k_init(const void* ei) {
    if (blockIdx.x == 0) {
        __shared__ int bad;
        if (threadIdx.x == 0) bad = 0;
        __syncthreads();
        long long pos = (long long)threadIdx.x * (NE / 256);
        long long v = ((const long long*)ei)[pos];
        if (v < 0 || v >= NN) atomicOr(&bad, 1);
        __syncthreads();
        if (threadIdx.x == 0) g_is64 = bad ? 0 : 1;
    }
    int i = blockIdx.x * blockDim.x + threadIdx.x;
    if (i < NN) g_degi[i] = 0;
}

// #2: count degrees AND scatter source ids into fixed-stride segments.
__global__ void k_deg_store(const void* __restrict__ ei) {
    int t = blockIdx.x * blockDim.x + threadIdx.x;
    long long e = (long long)t * 4;
    if (e >= NE) return;
    int is64 = g_is64;
    int4 r4 = load_idx4(ei, e, is64);
    int4 c4 = load_idx4(ei, (long long)NE + e, is64);
    int rr[4] = {r4.x, r4.y, r4.z, r4.w};
    int cc[4] = {c4.x, c4.y, c4.z, c4.w};
    #pragma unroll
    for (int k = 0; k < 4; k++) {
        int rk = atomicAdd(&g_degi[cc[k]], 1);
        if (rk < MAXDEG) g_nbr2[cc[k] * MAXDEG + rk] = rr[k];
    }
}

// #3: layer-1 transform (16 nodes/block) + dinv computation.
#define XS_STR 132
__global__ void k_xform1(const float* __restrict__ x, const float* __restrict__ W1) {
    __shared__ float sX[16 * XS_STR];
    __shared__ float sWt[HID * XS_STR];
    const float* xb = x + (size_t)blockIdx.x * 16 * CIN;
    #pragma unroll
    for (int L = threadIdx.x; L < 16 * CIN; L += 256) {
        int n = L >> 7, k = L & 127;
        sX[n * XS_STR + k] = xb[L];
    }
    #pragma unroll
    for (int L = threadIdx.x; L < CIN * HID; L += 256) {
        int k = L >> 4, j = L & 15;
        sWt[j * XS_STR + k] = W1[L];
    }
    __syncthreads();
    int nloc = threadIdx.x >> 4;
    int j    = threadIdx.x & 15;
    int node = blockIdx.x * 16 + nloc;
    const float4* xr = (const float4*)(sX  + nloc * XS_STR);
    const float4* wr = (const float4*)(sWt + j    * XS_STR);
    float acc = 0.f;
    #pragma unroll
    for (int k4 = 0; k4 < CIN / 4; k4++) {
        float4 xv = xr[k4];
        float4 wv = wr[k4];
        acc = fmaf(xv.x, wv.x, acc);
        acc = fmaf(xv.y, wv.y, acc);
        acc = fmaf(xv.z, wv.z, acc);
        acc = fmaf(xv.w, wv.w, acc);
    }
    float dv = rsqrtf(1.0f + (float)g_degi[node]);
    if (j == 0) g_dinv[node] = dv;
    float v = acc * dv;
    int tid = blockIdx.x * 256 + threadIdx.x;
    ((__half*)g_feat)[tid] = __float2half(v);
    g_agg[tid] = v;
}

// #4: pull layer 1 + fused layer-2. Warp per node; 8 lanes per row (half2 each),
// 4 neighbors per iteration (one per lane-quarter).
__global__ void k_pull1(const float* __restrict__ W2, const float* __restrict__ b1) {
    __shared__ float2 sW2[HID * 8];   // sW2[k*8+jj] = (W2[k][2jj], W2[k][2jj+1])
    __shared__ float2 sb2[8];
    for (int L = threadIdx.x; L < HID * 8; L += blockDim.x) {
        int k = L >> 3, jj = L & 7;
        sW2[L] = make_float2(W2[k * HID + 2*jj], W2[k * HID + 2*jj + 1]);
    }
    if (threadIdx.x < 8)
        sb2[threadIdx.x] = make_float2(b1[2*threadIdx.x], b1[2*threadIdx.x + 1]);
    __syncthreads();

    int warp = (blockIdx.x * blockDim.x + threadIdx.x) >> 5;
    if (warp >= NN) return;
    int lane = threadIdx.x & 31;
    int jj   = lane & 7;
    int qt   = lane >> 3;             // 0..3
    int start = warp * MAXDEG;
    int deg   = min(g_degi[warp], MAXDEG);
    float2 acc = make_float2(0.f, 0.f);
    for (int base = 0; base < deg; base += 32) {
        int myn = (base + lane < deg) ? g_nbr2[start + base + lane] : 0;
        int lim = min(32, deg - base);
        #pragma unroll 8
        for (int k = 0; k < 32; k += 4) {
            if (k >= lim) break;
            int r = __shfl_sync(0xffffffffu, myn, k + qt);
            if (k + qt < lim) {
                float2 f = __half22float2(g_feat[(size_t)r * 8 + jj]);
                acc.x += f.x; acc.y += f.y;
            }
        }
    }
    acc.x += __shfl_xor_sync(0xffffffffu, acc.x, 8);
    acc.y += __shfl_xor_sync(0xffffffffu, acc.y, 8);
    acc.x += __shfl_xor_sync(0xffffffffu, acc.x, 16);
    acc.y += __shfl_xor_sync(0xffffffffu, acc.y, 16);
    // ---- fused layer-2 transform (all lanes compute; lanes 0-7 write) ----
    float dv = g_dinv[warp];
    float2 ag = *(const float2*)(g_agg + (size_t)warp * HID + 2*jj);
    float2 bb = sb2[jj];
    float2 hv;
    hv.x = fmaxf(fmaf(dv, ag.x + acc.x, bb.x), 0.f);
    hv.y = fmaxf(fmaf(dv, ag.y + acc.y, bb.y), 0.f);
    float2 ov = make_float2(0.f, 0.f);
    #pragma unroll
    for (int kk = 0; kk < 8; kk++) {
        float hx = __shfl_sync(0xffffffffu, hv.x, kk);
        float hy = __shfl_sync(0xffffffffu, hv.y, kk);
        float2 w0 = sW2[(2*kk    ) * 8 + jj];
        float2 w1 = sW2[(2*kk + 1) * 8 + jj];
        ov.x = fmaf(hx, w0.x, fmaf(hy, w1.x, ov.x));
        ov.y = fmaf(hx, w0.y, fmaf(hy, w1.y, ov.y));
    }
    ov.x *= dv; ov.y *= dv;
    if (lane < 8) {
        g_feat2[(size_t)warp * 8 + jj] = __floats2half2_rn(ov.x, ov.y);
        *(float2*)(g_agg + (size_t)warp * HID + 2*jj) = ov;
    }
}

// #5: pull layer 2 + fused h2 (fp16 out). Warp per node.
__global__ void k_pull2(const float* __restrict__ b2) {
    __shared__ float2 sb2[8];
    if (threadIdx.x < 8)
        sb2[threadIdx.x] = make_float2(b2[2*threadIdx.x], b2[2*threadIdx.x + 1]);
    __syncthreads();
    int warp = (blockIdx.x * blockDim.x + threadIdx.x) >> 5;
    if (warp >= NN) return;
    int lane = threadIdx.x & 31;
    int jj   = lane & 7;
    int qt   = lane >> 3;
    int start = warp * MAXDEG;
    int deg   = min(g_degi[warp], MAXDEG);
    float2 acc = make_float2(0.f, 0.f);
    for (int base = 0; base < deg; base += 32) {
        int myn = (base + lane < deg) ? g_nbr2[start + base + lane] : 0;
        int lim = min(32, deg - base);
        #pragma unroll 8
        for (int k = 0; k < 32; k += 4) {
            if (k >= lim) break;
            int r = __shfl_sync(0xffffffffu, myn, k + qt);
            if (k + qt < lim) {
                float2 f = __half22float2(g_feat2[(size_t)r * 8 + jj]);
                acc.x += f.x; acc.y += f.y;
            }
        }
    }
    acc.x += __shfl_xor_sync(0xffffffffu, acc.x, 8);
    acc.y += __shfl_xor_sync(0xffffffffu, acc.y, 8);
    acc.x += __shfl_xor_sync(0xffffffffu, acc.x, 16);
    acc.y += __shfl_xor_sync(0xffffffffu, acc.y, 16);
    if (lane < 8) {
        float dv = g_dinv[warp];
        float2 ag = *(const float2*)(g_agg + (size_t)warp * HID + 2*jj);
        float2 bb = sb2[jj];
        float hx = fmaf(dv, ag.x + acc.x, bb.x);
        float hy = fmaf(dv, ag.y + acc.y, bb.y);
        ((half2*)g_h2)[(size_t)warp * 8 + jj] = __floats2half2_rn(hx, hy);
    }
}

// #6: score, 2 lanes per edge; fp16 rows = 1 sector per row.
__global__ void k_score(const void* __restrict__ ei, float* __restrict__ out) {
    int t = blockIdx.x * blockDim.x + threadIdx.x;
    long long e = t >> 1;
    if (e >= NE) return;
    int p = t & 1;
    int is64 = g_is64;
    int r = load_idx1(ei, e, is64);
    int c = load_idx1(ei, (long long)NE + e, is64);
    uint4 av = __ldg(&g_h2[(size_t)r * 2 + p]);
    uint4 bv = __ldg(&g_h2[(size_t)c * 2 + p]);
    const half2* ah = (const half2*)&av;
    const half2* bh = (const half2*)&bv;
    float s = 0.f;
    #pragma unroll
    for (int q = 0; q < 4; q++) {
        float2 a = __half22float2(ah[q]);
        float2 b = __half22float2(bh[q]);
        s = fmaf(a.x, b.x, fmaf(a.y, b.y, s));
    }
    s += __shfl_xor_sync(0xffffffffu, s, 1);
    if (p == 0) out[e] = 1.0f / (1.0f + __expf(-s));
}

extern "C" void kernel_launch(void* const* d_in, const int* in_sizes, int n_in,
                              void* d_out, int out_size) {
    const float* x  = nullptr;
    const void*  ei = nullptr;
    const float* W1 = nullptr;
    const float* b1 = nullptr;
    const float* W2 = nullptr;
    const float* b2 = nullptr;
    for (int i = 0; i < n_in; i++) {
        long long n = in_sizes[i];
        if      (n == (long long)NN * CIN)      x  = (const float*)d_in[i];
        else if (n == 2LL * NE)                 ei = d_in[i];
        else if (n == CIN * HID)                W1 = (const float*)d_in[i];
        else if (n == HID * HID)                W2 = (const float*)d_in[i];
        else if (n == HID) { if (!b1) b1 = (const float*)d_in[i]; else b2 = (const float*)d_in[i]; }
    }
    float* out = (float*)d_out;

    const int TB  = 256;
    const int gn  = (NN + TB - 1) / TB;
    const int ge4 = (NE / 4 + TB - 1) / TB;
    const int gw  = (NN * 32 + TB - 1) / TB;            // warp per node
    const int gs  = ((long long)NE * 2 + TB - 1) / TB;  // 2 lanes per edge

    k_init     <<<gn,  TB>>>(ei);           // #1 (zero + detect)
    k_deg_store<<<ge4, TB>>>(ei);           // #2
    k_xform1   <<<NN/16, TB>>>(x, W1);      // #3 (+ dinv)
    k_pull1    <<<gw,  TB>>>(W2, b1);       // #4  <- profiler slot
    k_pull2    <<<gw,  TB>>>(b2);           // #5
    k_score    <<<gs,  TB>>>(ei, out);      // #6
}